// round 2
// baseline (speedup 1.0000x reference)
#include <cuda_runtime.h>

#define IW 3072
#define IH 3072
#define NPIX (IW*IH)          // 9437184
#define W4 (IW/4)             // 768
#define NBIN 32768
#define HBLK 296              // histogram blocks (<= 32K px/block => u16-safe)

// ---------------- scratch (static device memory; no allocs) ----------------
__device__ __align__(128) float g_gray[NPIX];          // gray, later |grad|
__device__ __align__(128) float g_tmp[NPIX];           // separable-pass temp
__device__ __align__(128) float g_buf[NPIX];           // blurred, later ed
__device__ __align__(128) unsigned short g_code[NPIX]; // color code per pixel
__device__ __align__(128) unsigned int g_part[HBLK * (NBIN/2)]; // packed u16 partial hists
__device__ unsigned int g_counts[NBIN];
__device__ float g_cn[NBIN];
__device__ unsigned int g_magmax_bits;
__device__ unsigned int g_edmin_bits;
__device__ unsigned int g_edmax_bits;
__device__ unsigned int g_cntmin;
__device__ unsigned int g_cntmax;

// 15-tap 1D Gaussian (sigma=2), normalized; outer product == reference 2D kernel
__device__ __constant__ float GW[15] = {
    0.00043641f, 0.00221626f, 0.00876548f, 0.02699957f, 0.06476861f,
    0.12100369f, 0.17605932f, 0.19950135f, 0.17605932f, 0.12100369f,
    0.06476861f, 0.02699957f, 0.00876548f, 0.00221626f, 0.00043641f
};

__global__ void k_init() {
    g_magmax_bits = 0u;
    g_edmin_bits  = 0x7f7fffffu;  // +FLT_MAX bits (all ed >= 0)
    g_edmax_bits  = 0u;
    g_cntmin      = 0xffffffffu;
    g_cntmax      = 0u;
}

__device__ __forceinline__ unsigned int quant31(float v) {
    float q = rintf(v * 31.0f);               // round half-to-even == jnp.round
    q = fminf(fmaxf(q, 0.0f), 31.0f);
    return (unsigned int)q;
}

// ---- K1: gray + color code + privatized histogram (packed u16 in smem) ----
__global__ void k_gray_hist(const float* __restrict__ img) {
    extern __shared__ unsigned int sh[];      // NBIN/2 packed words = 64KB
    for (int i = threadIdx.x; i < NBIN/2; i += blockDim.x) sh[i] = 0u;
    __syncthreads();

    const int T  = gridDim.x * blockDim.x;
    const int gt = blockIdx.x * blockDim.x + threadIdx.x;
    const float4* r4 = (const float4*)img;
    const float4* g4 = (const float4*)(img + NPIX);
    const float4* b4 = (const float4*)(img + 2*NPIX);
    float4*  gray4 = (float4*)g_gray;
    ushort4* code4 = (ushort4*)g_code;

    for (int i = gt; i < NPIX/4; i += T) {
        float4 r = r4[i], g = g4[i], b = b4[i];
        float4 gr;
        gr.x = 0.299f*r.x + 0.587f*g.x + 0.114f*b.x;
        gr.y = 0.299f*r.y + 0.587f*g.y + 0.114f*b.y;
        gr.z = 0.299f*r.z + 0.587f*g.z + 0.114f*b.z;
        gr.w = 0.299f*r.w + 0.587f*g.w + 0.114f*b.w;
        gray4[i] = gr;

        unsigned int c0 = quant31(r.x)*1024u + quant31(g.x)*32u + quant31(b.x);
        unsigned int c1 = quant31(r.y)*1024u + quant31(g.y)*32u + quant31(b.y);
        unsigned int c2 = quant31(r.z)*1024u + quant31(g.z)*32u + quant31(b.z);
        unsigned int c3 = quant31(r.w)*1024u + quant31(g.w)*32u + quant31(b.w);
        ushort4 uc; uc.x=(unsigned short)c0; uc.y=(unsigned short)c1;
                    uc.z=(unsigned short)c2; uc.w=(unsigned short)c3;
        code4[i] = uc;

        atomicAdd(&sh[c0 >> 1], 1u << ((c0 & 1u) << 4));
        atomicAdd(&sh[c1 >> 1], 1u << ((c1 & 1u) << 4));
        atomicAdd(&sh[c2 >> 1], 1u << ((c2 & 1u) << 4));
        atomicAdd(&sh[c3 >> 1], 1u << ((c3 & 1u) << 4));
    }
    __syncthreads();
    unsigned int* p = g_part + (size_t)blockIdx.x * (NBIN/2);
    for (int i = threadIdx.x; i < NBIN/2; i += blockDim.x) p[i] = sh[i];
}

// ---- K2a: reduce partial histograms, track min(nonzero)/max count ----
__global__ void k_hist_reduce() {
    int w = blockIdx.x * blockDim.x + threadIdx.x;  // 0..16383 (packed word)
    unsigned int lo = 0, hi = 0;
    for (int b = 0; b < HBLK; b++) {
        unsigned int p = g_part[(size_t)b * (NBIN/2) + w];
        lo += p & 0xffffu;
        hi += p >> 16;
    }
    g_counts[2*w]   = lo;
    g_counts[2*w+1] = hi;
    unsigned int mn = 0xffffffffu, mx = 0u;
    if (lo) { mn = min(mn, lo); mx = max(mx, lo); }
    if (hi) { mn = min(mn, hi); mx = max(mx, hi); }
    #pragma unroll
    for (int o = 16; o; o >>= 1) {
        mn = min(mn, __shfl_xor_sync(0xffffffffu, mn, o));
        mx = max(mx, __shfl_xor_sync(0xffffffffu, mx, o));
    }
    if ((threadIdx.x & 31) == 0) {
        atomicMin(&g_cntmin, mn);
        atomicMax(&g_cntmax, mx);
    }
}

__device__ __forceinline__ float cs_of(unsigned int c) {
    return -logf((float)c / 9437184.0f + 1e-9f) * 1.5f;
}

// ---- K2b: precompute normalized color-sparsity per bin ----
__global__ void k_cn_table() {
    int bin = blockIdx.x * blockDim.x + threadIdx.x;
    float csmin = cs_of(g_cntmax);     // -log monotone decreasing in count
    float csmax = cs_of(g_cntmin);
    float cs = cs_of(g_counts[bin]);
    g_cn[bin] = (cs - csmin) / (csmax - csmin + 1e-9f);
}

// ---- K3: horizontal 5-tap box (sum only) ----
__global__ void k_boxh() {
    int t = blockIdx.x * blockDim.x + threadIdx.x;   // W4*IH threads
    int y = t / W4, xc = t % W4;
    const float4* in = (const float4*)g_gray + (size_t)y * W4;
    float4 M = in[xc];
    float4 L = (xc > 0)      ? in[xc-1] : make_float4(0,0,0,0);
    float4 R = (xc < W4 - 1) ? in[xc+1] : make_float4(0,0,0,0);
    float v0=L.z, v1=L.w, v2=M.x, v3=M.y, v4=M.z, v5=M.w, v6=R.x, v7=R.y;
    float4 o;
    o.x = v0+v1+v2+v3+v4;
    o.y = v1+v2+v3+v4+v5;
    o.z = v2+v3+v4+v5+v6;
    o.w = v3+v4+v5+v6+v7;
    ((float4*)g_tmp)[t] = o;
}

// ---- K4: vertical 5-tap box * (1/25) ----
__global__ void k_boxv() {
    int t = blockIdx.x * blockDim.x + threadIdx.x;   // W4*(IH/4) threads
    int xc = t % W4, y0 = (t / W4) * 4;
    const float4* in = (const float4*)g_tmp;
    float4 r[8];
    #pragma unroll
    for (int k = 0; k < 8; k++) {
        int row = y0 - 2 + k;
        r[k] = (row >= 0 && row < IH) ? in[(size_t)row * W4 + xc] : make_float4(0,0,0,0);
    }
    float4* out = (float4*)g_buf;
    #pragma unroll
    for (int j = 0; j < 4; j++) {
        float4 o;
        o.x = (r[j].x+r[j+1].x+r[j+2].x+r[j+3].x+r[j+4].x)*0.04f;
        o.y = (r[j].y+r[j+1].y+r[j+2].y+r[j+3].y+r[j+4].y)*0.04f;
        o.z = (r[j].z+r[j+1].z+r[j+2].z+r[j+3].z+r[j+4].z)*0.04f;
        o.w = (r[j].w+r[j+1].w+r[j+2].w+r[j+3].w+r[j+4].w)*0.04f;
        out[(size_t)(y0+j) * W4 + xc] = o;
    }
}

// ---- K5: Sobel magnitude + global max ----
__global__ void k_sobel() {
    int t = blockIdx.x * blockDim.x + threadIdx.x;   // W4*(IH/4)
    int xc = t % W4, y0 = (t / W4) * 4;
    int x0 = xc * 4;
    float dxr[6][4], sxr[6][4];
    #pragma unroll
    for (int k = 0; k < 6; k++) {
        int row = y0 - 1 + k;
        float s0, s1, s2, s3, s4, s5;
        if (row >= 0 && row < IH) {
            const float* rp = g_buf + (size_t)row * IW;
            float4 M = *(const float4*)(rp + x0);
            s0 = (x0 > 0)       ? rp[x0 - 1] : 0.0f;
            s5 = (x0 + 4 < IW)  ? rp[x0 + 4] : 0.0f;
            s1 = M.x; s2 = M.y; s3 = M.z; s4 = M.w;
        } else { s0=s1=s2=s3=s4=s5=0.0f; }
        dxr[k][0]=s2-s0; dxr[k][1]=s3-s1; dxr[k][2]=s4-s2; dxr[k][3]=s5-s3;
        sxr[k][0]=s0+2.0f*s1+s2; sxr[k][1]=s1+2.0f*s2+s3;
        sxr[k][2]=s2+2.0f*s3+s4; sxr[k][3]=s3+2.0f*s4+s5;
    }
    float mloc = 0.0f;
    #pragma unroll
    for (int j = 0; j < 4; j++) {
        float oo[4];
        #pragma unroll
        for (int c = 0; c < 4; c++) {
            float gx = dxr[j][c] + 2.0f*dxr[j+1][c] + dxr[j+2][c];
            float gy = sxr[j+2][c] - sxr[j][c];
            float m = sqrtf(gx*gx + gy*gy);
            oo[c] = m; mloc = fmaxf(mloc, m);
        }
        ((float4*)g_gray)[(size_t)(y0+j) * W4 + xc] = make_float4(oo[0],oo[1],oo[2],oo[3]);
    }
    #pragma unroll
    for (int o = 16; o; o >>= 1) mloc = fmaxf(mloc, __shfl_xor_sync(0xffffffffu, mloc, o));
    if ((threadIdx.x & 31) == 0) atomicMax(&g_magmax_bits, __float_as_uint(mloc));
}

// ---- K6: threshold to edge map + horizontal 15-tap Gaussian ----
__global__ void k_gaussh() {
    int t = blockIdx.x * blockDim.x + threadIdx.x;   // W4*IH
    int y = t / W4, xc = t % W4;
    float mx = __uint_as_float(g_magmax_bits);
    float hi = mx * 0.2f, lo = hi * 0.3f;
    const float4* in = (const float4*)g_gray + (size_t)y * W4;
    float e[20];
    #pragma unroll
    for (int q = 0; q < 5; q++) {
        int xq = xc + q - 2;
        float4 v = (xq >= 0 && xq < W4) ? in[xq] : make_float4(0,0,0,0);
        e[q*4+0] = (v.x > lo && v.x < hi) ? 1.0f : 0.0f;
        e[q*4+1] = (v.y > lo && v.y < hi) ? 1.0f : 0.0f;
        e[q*4+2] = (v.z > lo && v.z < hi) ? 1.0f : 0.0f;
        e[q*4+3] = (v.w > lo && v.w < hi) ? 1.0f : 0.0f;
    }
    float oo[4];
    #pragma unroll
    for (int j = 0; j < 4; j++) {
        float s = 0.0f;
        #pragma unroll
        for (int k = 0; k < 15; k++) s += GW[k] * e[j + 1 + k];
        oo[j] = s;
    }
    ((float4*)g_tmp)[t] = make_float4(oo[0], oo[1], oo[2], oo[3]);
}

__device__ __forceinline__ void fma4(float4& acc, float wt, const float4& r) {
    acc.x += wt * r.x; acc.y += wt * r.y; acc.z += wt * r.z; acc.w += wt * r.w;
}

// ---- K7: vertical 15-tap Gaussian + ed min/max ----
__global__ void k_gaussv() {
    int t = blockIdx.x * blockDim.x + threadIdx.x;   // W4*(IH/4)
    int xc = t % W4, y0 = (t / W4) * 4;
    const float4* in = (const float4*)g_tmp;
    float4 a0 = make_float4(0,0,0,0), a1 = a0, a2 = a0, a3 = a0;
    #pragma unroll
    for (int k = 0; k < 18; k++) {
        int row = y0 - 7 + k;
        float4 r = (row >= 0 && row < IH) ? in[(size_t)row * W4 + xc] : make_float4(0,0,0,0);
        if (k <= 14)           fma4(a0, GW[k],   r);
        if (k >= 1 && k <= 15) fma4(a1, GW[k-1], r);
        if (k >= 2 && k <= 16) fma4(a2, GW[k-2], r);
        if (k >= 3)            fma4(a3, GW[k-3], r);
    }
    float4* out = (float4*)g_buf;
    out[(size_t)(y0+0)*W4+xc] = a0;
    out[(size_t)(y0+1)*W4+xc] = a1;
    out[(size_t)(y0+2)*W4+xc] = a2;
    out[(size_t)(y0+3)*W4+xc] = a3;

    float mn =       fminf(fminf(fminf(a0.x,a0.y),fminf(a0.z,a0.w)),
               fminf(fminf(fminf(a1.x,a1.y),fminf(a1.z,a1.w)),
               fminf(fminf(fminf(a2.x,a2.y),fminf(a2.z,a2.w)),
                     fminf(fminf(a3.x,a3.y),fminf(a3.z,a3.w)))));
    float mxv =      fmaxf(fmaxf(fmaxf(a0.x,a0.y),fmaxf(a0.z,a0.w)),
               fmaxf(fmaxf(fmaxf(a1.x,a1.y),fmaxf(a1.z,a1.w)),
               fmaxf(fmaxf(fmaxf(a2.x,a2.y),fmaxf(a2.z,a2.w)),
                     fmaxf(fmaxf(a3.x,a3.y),fmaxf(a3.z,a3.w)))));
    #pragma unroll
    for (int o = 16; o; o >>= 1) {
        mn  = fminf(mn,  __shfl_xor_sync(0xffffffffu, mn,  o));
        mxv = fmaxf(mxv, __shfl_xor_sync(0xffffffffu, mxv, o));
    }
    if ((threadIdx.x & 31) == 0) {
        atomicMin(&g_edmin_bits, __float_as_uint(mn));   // all values >= 0
        atomicMax(&g_edmax_bits, __float_as_uint(mxv));
    }
}

// ---- K8: final sigmoid(alpha*en + beta*cn[code]) with smem cn table ----
__global__ void k_final(const float* __restrict__ alpha_p,
                        const float* __restrict__ beta_p,
                        float* __restrict__ out) {
    extern __shared__ float s_cn[];                 // 32768 floats = 128KB
    for (int i = threadIdx.x; i < NBIN; i += blockDim.x) s_cn[i] = g_cn[i];
    __syncthreads();
    float alpha = *alpha_p, beta = *beta_p;
    float edmin = __uint_as_float(g_edmin_bits);
    float edmax = __uint_as_float(g_edmax_bits);
    float inv = 1.0f / (edmax - edmin + 1e-9f);

    const float4*  ed4 = (const float4*)g_buf;
    const ushort4* c4  = (const ushort4*)g_code;
    float4* o4 = (float4*)out;
    int T = gridDim.x * blockDim.x;
    for (int i = blockIdx.x * blockDim.x + threadIdx.x; i < NPIX/4; i += T) {
        float4 ed = ed4[i];
        ushort4 c = c4[i];
        float x0 = alpha * ((ed.x - edmin) * inv) + beta * s_cn[c.x];
        float x1 = alpha * ((ed.y - edmin) * inv) + beta * s_cn[c.y];
        float x2 = alpha * ((ed.z - edmin) * inv) + beta * s_cn[c.z];
        float x3 = alpha * ((ed.w - edmin) * inv) + beta * s_cn[c.w];
        float4 o;
        o.x = 1.0f / (1.0f + expf(-x0));
        o.y = 1.0f / (1.0f + expf(-x1));
        o.z = 1.0f / (1.0f + expf(-x2));
        o.w = 1.0f / (1.0f + expf(-x3));
        o4[i] = o;
    }
}

extern "C" void kernel_launch(void* const* d_in, const int* in_sizes, int n_in,
                              void* d_out, int out_size) {
    const float* img   = (const float*)d_in[0];
    const float* alpha = (const float*)d_in[1];
    const float* beta  = (const float*)d_in[2];
    float* out = (float*)d_out;

    // Opt-in >48KB dynamic smem (idempotent host-state calls, graph-safe)
    cudaFuncSetAttribute(k_gray_hist, cudaFuncAttributeMaxDynamicSharedMemorySize, (NBIN/2)*4);
    cudaFuncSetAttribute(k_final,     cudaFuncAttributeMaxDynamicSharedMemorySize, NBIN*4);

    k_init<<<1, 1>>>();
    k_gray_hist<<<HBLK, 256, (NBIN/2)*4>>>(img);
    k_hist_reduce<<<(NBIN/2)/256, 256>>>();
    k_cn_table<<<NBIN/256, 256>>>();
    k_boxh<<<(W4*IH)/256, 256>>>();
    k_boxv<<<(W4*(IH/4))/256, 256>>>();
    k_sobel<<<(W4*(IH/4))/256, 256>>>();
    k_gaussh<<<(W4*IH)/256, 256>>>();
    k_gaussv<<<(W4*(IH/4))/256, 256>>>();
    k_final<<<148, 1024, NBIN*4>>>(alpha, beta, out);
}